// round 13
// baseline (speedup 1.0000x reference)
#include <cuda_runtime.h>
#include <stdint.h>

#define B_DIM 4
#define C_DIM 2
#define E_DIM 256
#define L_DIM 16000
#define W_DIM 40
#define STEP  20
#define T_DIM ((L_DIM - 1) * STEP + W_DIM)   // 320020
#define NT    128
#define WARPS 4
#define MTILE 128                  // l's per CTA (32 per warp)
#define LTILES (L_DIM / MTILE)     // 125

#define KC      16
#define NSTAGE  (E_DIM / KC)       // 16
#define PITCH   40                 // words; 8*tig+g conflict-free pattern

#define TILE_W   (KC * PITCH)          // 640 words: one 16e x 32l tile
#define WBUF_W   (3 * TILE_W)          // 1920: mix, mask0, mask1
#define WREG_W   (2 * WBUF_W)          // 3840 per warp (double buffer)
#define BAS_OFF  (WARPS * WREG_W)      // 15360
#define SB_WORDS (E_DIM * PITCH)       // 10240 (tf32 basis [e][w])
#define TOTAL_W  (BAS_OFF + SB_WORDS)  // 25600
#define SMEM_BYTES (TOTAL_W * 4)       // 102400
#define PITCH_D  40

#define NSTRIPS (B_DIM * C_DIM * (LTILES - 1))     // 992 CTA-boundary strips

__device__ __forceinline__ uint32_t f2tf32(float f) {
    uint32_t u;
    asm("cvt.rna.tf32.f32 %0, %1;" : "=r"(u) : "f"(f));
    return u;
}
__device__ __forceinline__ void mma_tf32(float* d, const uint32_t* a, const uint32_t* b) {
    asm volatile(
        "mma.sync.aligned.m16n8k8.row.col.f32.tf32.tf32.f32 "
        "{%0,%1,%2,%3}, {%4,%5,%6,%7}, {%8,%9}, {%0,%1,%2,%3};"
        : "+f"(d[0]), "+f"(d[1]), "+f"(d[2]), "+f"(d[3])
        : "r"(a[0]), "r"(a[1]), "r"(a[2]), "r"(a[3]), "r"(b[0]), "r"(b[1]));
}
__device__ __forceinline__ void cp16(uint32_t dst_smem, const void* src) {
    asm volatile("cp.async.cg.shared.global [%0], [%1], 16;" :: "r"(dst_smem), "l"(src));
}
__device__ __forceinline__ void cp_commit() {
    asm volatile("cp.async.commit_group;" ::: "memory");
}
__device__ __forceinline__ void cp_wait1() {
    asm volatile("cp.async.wait_group 1;" ::: "memory");
}

// ---------- zero only the CTA-boundary strips (atomic targets) ----------
__global__ void zero_strips_kernel(float* __restrict__ out) {
    int i = blockIdx.x * blockDim.x + threadIdx.x;
    if (i < NSTRIPS * STEP) {
        int j  = i % STEP;
        int s  = i / STEP;
        int bc = s / (LTILES - 1);
        int k  = s % (LTILES - 1) + 1;            // boundary ltile 1..124
        out[(size_t)bc * T_DIM + (size_t)k * MTILE * STEP + j] = 0.f;
    }
}

__global__ void __launch_bounds__(NT, 2)
decoder_kernel(const float* __restrict__ mix,
               const float* __restrict__ mask,
               const float* __restrict__ basis,
               float* __restrict__ out) {
    extern __shared__ __align__(16) uint32_t smem[];
    const uint32_t smem_base = (uint32_t)__cvta_generic_to_shared(smem);
    float*    sF = reinterpret_cast<float*>(smem);
    uint32_t* sB = smem + BAS_OFF;                       // tf32 basis [e][w]
    float*    sD = reinterpret_cast<float*>(smem + BAS_OFF);  // epilogue overlay

    const int tid  = threadIdx.x;
    const int wid  = tid >> 5;
    const int lane = tid & 31;
    const int g    = lane >> 2;
    const int tig  = lane & 3;

    const int b     = blockIdx.x & 3;
    const int ltile = blockIdx.x >> 2;
    const int warp_l = ltile * MTILE + wid * 32;

    // ---- one-time: basis -> SMEM as tf32 [e][w] (only CTA barrier pre-loop) ----
    for (int i = tid; i < W_DIM * E_DIM; i += NT) {
        int w = i >> 8, e = i & 255;                 // basis is [W][E]
        sB[e * PITCH + w] = f2tf32(basis[i]);
    }
    __syncthreads();

    const float* pmix = mix  + (size_t)b * E_DIM * L_DIM + warp_l;
    const float* pmk0 = mask + ((size_t)b * C_DIM + 0) * E_DIM * L_DIM + warp_l;
    const float* pmk1 = pmk0 + (size_t)E_DIM * L_DIM;

    const uint32_t wbase = smem_base + wid * WREG_W * 4;   // my private region
    const float*   fbase = sF + wid * WREG_W;

    // ---- warp-private stage issuer: 12 cp16 per lane per stage ----
    auto issue_stage = [&](int s) {
        if (s < NSTAGE) {
            const uint32_t dst = wbase + (uint32_t)(s & 1) * (WBUF_W * 4);
            const size_t eoff = (size_t)s * KC * L_DIM;
#pragma unroll
            for (int i = 0; i < 4; ++i) {
                const int q = lane + 32 * i;           // 0..127 quads per tile
                const int e = q >> 3, l4 = (q & 7) * 4;
                const uint32_t doff = (uint32_t)(e * PITCH + l4) * 4;
                const size_t  soff = eoff + (size_t)e * L_DIM + l4;
                cp16(dst + doff,                  pmix + soff);
                cp16(dst + TILE_W * 4 + doff,     pmk0 + soff);
                cp16(dst + 2 * TILE_W * 4 + doff, pmk1 + soff);
            }
        }
        cp_commit();   // empty groups past the end keep wait counts uniform
    };

    float acc[2][2][5][4];   // [ch][mt][nt][reg]
#pragma unroll
    for (int ch = 0; ch < 2; ++ch)
#pragma unroll
        for (int mt = 0; mt < 2; ++mt)
#pragma unroll
            for (int nt = 0; nt < 5; ++nt)
#pragma unroll
                for (int r = 0; r < 4; ++r) acc[ch][mt][nt][r] = 0.f;

    issue_stage(0);
    issue_stage(1);

#pragma unroll 1
    for (int st = 0; st < NSTAGE; ++st) {
        cp_wait1();        // my stage-st copies landed (st+1 still in flight)
        __syncwarp();      // all lanes waited -> whole warp tile visible

        const float* fMix = fbase + (st & 1) * WBUF_W;
        const float* fM0  = fMix + TILE_W;
        const float* fM1  = fMix + 2 * TILE_W;

        // ---- hoist all frag loads/converts for the stage (both ks) ----
        uint32_t a0[2][2][4], a1[2][2][4];   // [ks][mt][reg] per channel
        uint32_t bf[2][5][2];
#pragma unroll
        for (int ks = 0; ks < 2; ++ks) {
            const int kb = ks * 8;
            const int r1 = (kb + tig) * PITCH;
            const int r2 = (kb + tig + 4) * PITCH;
#pragma unroll
            for (int mt = 0; mt < 2; ++mt) {
                const int m0 = mt * 16 + g;
                float mx0 = fMix[r1 + m0], mx1 = fMix[r1 + m0 + 8];
                float mx2 = fMix[r2 + m0], mx3 = fMix[r2 + m0 + 8];
                a0[ks][mt][0] = f2tf32(mx0 * fM0[r1 + m0]);
                a0[ks][mt][1] = f2tf32(mx1 * fM0[r1 + m0 + 8]);
                a0[ks][mt][2] = f2tf32(mx2 * fM0[r2 + m0]);
                a0[ks][mt][3] = f2tf32(mx3 * fM0[r2 + m0 + 8]);
                a1[ks][mt][0] = f2tf32(mx0 * fM1[r1 + m0]);
                a1[ks][mt][1] = f2tf32(mx1 * fM1[r1 + m0 + 8]);
                a1[ks][mt][2] = f2tf32(mx2 * fM1[r2 + m0]);
                a1[ks][mt][3] = f2tf32(mx3 * fM1[r2 + m0 + 8]);
            }
            const uint32_t* pb = sB + (st * KC + kb + tig) * PITCH + g;
#pragma unroll
            for (int nt = 0; nt < 5; ++nt) {
                bf[ks][nt][0] = pb[nt * 8];
                bf[ks][nt][1] = pb[nt * 8 + 4 * PITCH];
            }
        }

        issue_stage(st + 2);   // buffer st&1 fully consumed into registers above

        // ---- 40 MMAs (B frags shared across channels) ----
#pragma unroll
        for (int ks = 0; ks < 2; ++ks)
#pragma unroll
            for (int mt = 0; mt < 2; ++mt)
#pragma unroll
                for (int nt = 0; nt < 5; ++nt) {
                    mma_tf32(acc[0][mt][nt], a0[ks][mt], bf[ks][nt]);
                    mma_tf32(acc[1][mt][nt], a1[ks][mt], bf[ks][nt]);
                }
    }

    // ---- write frags to D tile (overlay on basis region) ----
    __syncthreads();           // all warps done reading sB
#pragma unroll
    for (int ch = 0; ch < 2; ++ch)
#pragma unroll
        for (int mt = 0; mt < 2; ++mt)
#pragma unroll
            for (int nt = 0; nt < 5; ++nt) {
                int row = ch * MTILE + wid * 32 + mt * 16 + g;
                int col = nt * 8 + 2 * tig;
                *reinterpret_cast<float2*>(&sD[row * PITCH_D + col]) =
                    make_float2(acc[ch][mt][nt][0], acc[ch][mt][nt][1]);
                *reinterpret_cast<float2*>(&sD[(row + 8) * PITCH_D + col]) =
                    make_float2(acc[ch][mt][nt][2], acc[ch][mt][nt][3]);
            }
    __syncthreads();

    // ---- fused overlap-add epilogue: thread tid <-> l row, both channels ----
    const int l = ltile * MTILE + tid;
#pragma unroll 1
    for (int ch = 0; ch < 2; ++ch) {
        const int rr = ch * MTILE + tid;
        float lo[STEP], up[STEP];
#pragma unroll
        for (int q = 0; q < 5; ++q) {
            float4 v = *reinterpret_cast<float4*>(&sD[rr * PITCH_D + q * 4]);
            lo[4 * q] = v.x; lo[4 * q + 1] = v.y; lo[4 * q + 2] = v.z; lo[4 * q + 3] = v.w;
        }
        if (tid > 0) {
#pragma unroll
            for (int q = 0; q < 5; ++q) {
                float4 v = *reinterpret_cast<float4*>(&sD[(rr - 1) * PITCH_D + STEP + q * 4]);
                up[4 * q] = v.x; up[4 * q + 1] = v.y; up[4 * q + 2] = v.z; up[4 * q + 3] = v.w;
            }
        }

        const size_t base = ((size_t)b * C_DIM + ch) * T_DIM + (size_t)l * STEP;
        if (tid > 0) {
#pragma unroll
            for (int j = 0; j < STEP; ++j) out[base + j] = lo[j] + up[j];
        } else if (l == 0) {
#pragma unroll
            for (int j = 0; j < STEP; ++j) out[base + j] = lo[j];
        } else {
#pragma unroll
            for (int j = 0; j < STEP; ++j) atomicAdd(&out[base + j], lo[j]);
        }

        if (tid == MTILE - 1) {       // upper half has no in-CTA consumer
            float hi[STEP];
#pragma unroll
            for (int q = 0; q < 5; ++q) {
                float4 v = *reinterpret_cast<float4*>(&sD[rr * PITCH_D + STEP + q * 4]);
                hi[4 * q] = v.x; hi[4 * q + 1] = v.y; hi[4 * q + 2] = v.z; hi[4 * q + 3] = v.w;
            }
            if (l == L_DIM - 1) {
#pragma unroll
                for (int j = 0; j < STEP; ++j) out[base + STEP + j] = hi[j];
            } else {
#pragma unroll
                for (int j = 0; j < STEP; ++j) atomicAdd(&out[base + STEP + j], hi[j]);
            }
        }
    }
}

extern "C" void kernel_launch(void* const* d_in, const int* in_sizes, int n_in,
                              void* d_out, int out_size) {
    // Identify inputs by element count for robustness.
    const float *mix = nullptr, *mask = nullptr, *basis = nullptr;
    for (int i = 0; i < n_in; ++i) {
        long long s = in_sizes[i];
        if (s == (long long)B_DIM * E_DIM * L_DIM)              mix   = (const float*)d_in[i];
        else if (s == (long long)B_DIM * C_DIM * E_DIM * L_DIM) mask  = (const float*)d_in[i];
        else if (s == (long long)W_DIM * E_DIM)                 basis = (const float*)d_in[i];
    }
    float* out = (float*)d_out;

    zero_strips_kernel<<<(NSTRIPS * STEP + 255) / 256, 256>>>(out);

    cudaFuncSetAttribute(decoder_kernel,
                         cudaFuncAttributeMaxDynamicSharedMemorySize, SMEM_BYTES);
    decoder_kernel<<<B_DIM * LTILES, NT, SMEM_BYTES>>>(mix, mask, basis, out);
}

// round 14
// speedup vs baseline: 1.0331x; 1.0331x over previous
#include <cuda_runtime.h>
#include <stdint.h>

#define B_DIM 4
#define C_DIM 2
#define E_DIM 256
#define L_DIM 16000
#define W_DIM 40
#define STEP  20
#define T_DIM ((L_DIM - 1) * STEP + W_DIM)   // 320020
#define NT    256
#define MTILE 128                  // l's per CTA
#define LTILES (L_DIM / MTILE)     // 125

#define KC      16
#define NSTAGE  (E_DIM / KC)       // 16
#define NBUF    3
#define PITCH_A 136                // words; mod 32 == 8 -> conflict-free frag reads
#define PITCH_B 20                 // words; (nt*8+g)*20 + tig distinct mod 32
#define PITCH_D 40

#define SA_WORDS (KC * PITCH_A)        // 2176 per buffer
#define SB_WORDS (W_DIM * PITCH_B)     // 800 per buffer
#define MIX_OFF  0                                  // 3 bufs
#define MSK_OFF  (NBUF * SA_WORDS)                  // 6528; 3 bufs x 2 channels
#define BAS_OFF  (MSK_OFF + 2 * NBUF * SA_WORDS)    // 19584
#define BND_OFF  (BAS_OFF + NBUF * SB_WORDS)        // 21984: 40-word boundary frame
#define LOOP_WORDS (BND_OFF + C_DIM * STEP)         // 22024
#define SMEM_BYTES (LOOP_WORDS * 4)                 // 88096

__device__ __forceinline__ uint32_t f2tf32(float f) {
    uint32_t u;
    asm("cvt.rna.tf32.f32 %0, %1;" : "=r"(u) : "f"(f));
    return u;
}
__device__ __forceinline__ void mma_tf32(float* d, const uint32_t* a, const uint32_t* b) {
    asm volatile(
        "mma.sync.aligned.m16n8k8.row.col.f32.tf32.tf32.f32 "
        "{%0,%1,%2,%3}, {%4,%5,%6,%7}, {%8,%9}, {%0,%1,%2,%3};"
        : "+f"(d[0]), "+f"(d[1]), "+f"(d[2]), "+f"(d[3])
        : "r"(a[0]), "r"(a[1]), "r"(a[2]), "r"(a[3]), "r"(b[0]), "r"(b[1]));
}
__device__ __forceinline__ void cp16(uint32_t dst_smem, const void* src) {
    asm volatile("cp.async.cg.shared.global [%0], [%1], 16;" :: "r"(dst_smem), "l"(src));
}
__device__ __forceinline__ void cp_commit() {
    asm volatile("cp.async.commit_group;" ::: "memory");
}
__device__ __forceinline__ void cp_wait1() {
    asm volatile("cp.async.wait_group 1;" ::: "memory");
}

__global__ void __launch_bounds__(NT, 2)
decoder_kernel(const float* __restrict__ mix,
               const float* __restrict__ mask,
               const float* __restrict__ basis,
               float* __restrict__ out) {
    extern __shared__ __align__(16) uint32_t smem[];
    const uint32_t smem_base = (uint32_t)__cvta_generic_to_shared(smem);
    float* sF   = reinterpret_cast<float*>(smem);
    float* sD   = sF;                                // epilogue overlay (2*128*40 words)
    float* sBnd = sF + BND_OFF;                      // boundary frame [ch][20]

    const int tid  = threadIdx.x;
    const int wid  = tid >> 5;
    const int lane = tid & 31;
    const int g    = lane >> 2;
    const int tig  = lane & 3;

    const int b     = blockIdx.x & 3;
    const int ltile = blockIdx.x >> 2;

    const float* pmix = mix + (size_t)b * E_DIM * L_DIM + (size_t)ltile * MTILE;
    const float* pmk0 = mask + ((size_t)b * C_DIM + 0) * E_DIM * L_DIM + (size_t)ltile * MTILE;
    const float* pmk1 = pmk0 + (size_t)E_DIM * L_DIM;

    // staging coords: mix -> 2 quads/thread, mask -> my channel, 4 quads/thread
    const int mch  = tid >> 7;             // which mask channel this thread stages
    const int mt7  = tid & 127;
    const float* pmk = (mch == 0) ? pmk0 : pmk1;

    // ---- boundary column loads (frame l0-1), consumed only after the main loop ----
    // warp w: channel w>>2, 8 e's per lane. Scattered LDGs; latency hides under loop.
    const int wch = wid >> 2;
    float scol[8];
    if (ltile > 0) {
        const int lm1 = ltile * MTILE - 1;
        const float* cm = mix + (size_t)b * E_DIM * L_DIM + lm1;
        const float* ck = mask + ((size_t)b * C_DIM + wch) * E_DIM * L_DIM + lm1;
#pragma unroll
        for (int k = 0; k < 8; ++k) {
            const int e = lane + 32 * k;
            scol[k] = __ldg(cm + (size_t)e * L_DIM) * __ldg(ck + (size_t)e * L_DIM);
        }
    }

    float acc[2][5][4];
#pragma unroll
    for (int mt = 0; mt < 2; ++mt)
#pragma unroll
        for (int nt = 0; nt < 5; ++nt)
#pragma unroll
            for (int r = 0; r < 4; ++r) acc[mt][nt][r] = 0.f;

    // ---- stage issuer (cp.async) ----
    auto issue_stage = [&](int s) {
        if (s < NSTAGE) {
            const int buf = s % NBUF;
            const size_t eoff = (size_t)s * KC * L_DIM;
            const uint32_t dmix = smem_base + (MIX_OFF + buf * SA_WORDS) * 4;
            const uint32_t dmsk = smem_base + (MSK_OFF + (buf * 2 + mch) * SA_WORDS) * 4;
            // mix: 512 quads over 256 threads (2 each)
#pragma unroll
            for (int i = 0; i < 2; ++i) {
                const int q = tid + (i << 8);
                const int e = q >> 5, l4 = (q & 31) * 4;
                cp16(dmix + (uint32_t)(e * PITCH_A + l4) * 4,
                     pmix + eoff + (size_t)e * L_DIM + l4);
            }
            // mask (my channel): 512 quads over 128 threads (4 each)
#pragma unroll
            for (int i = 0; i < 4; ++i) {
                const int q = mt7 + (i << 7);
                const int e = q >> 5, l4 = (q & 31) * 4;
                cp16(dmsk + (uint32_t)(e * PITCH_A + l4) * 4,
                     pmk + eoff + (size_t)e * L_DIM + l4);
            }
            // basis chunk: 160 quads
            if (tid < 160) {
                const int w = tid >> 2, be = (tid & 3) * 4;
                const uint32_t dbas = smem_base + (BAS_OFF + buf * SB_WORDS) * 4;
                cp16(dbas + (uint32_t)(w * PITCH_B + be) * 4,
                     basis + (size_t)w * E_DIM + s * KC + be);
            }
        }
        cp_commit();   // empty groups past the end keep wait counts uniform
    };

    // prologue: stages 0 and 1 in flight
    issue_stage(0);
    issue_stage(1);

    const int mbase = (wid & 3) * 32;

#pragma unroll 1
    for (int st = 0; st < NSTAGE; ++st) {
        cp_wait1();                 // stage st landed (st+1 still in flight)
        __syncthreads();            // stage st visible; all warps past mma(st-1)
        issue_stage(st + 2);        // buf (st+2)%3 == (st-1)%3: freed by the sync above

        const int buf = st % NBUF;
        const float* fMix = sF + MIX_OFF + buf * SA_WORDS;
        const float* fMsk = sF + MSK_OFF + (buf * 2 + wch) * SA_WORDS;
        const float* fB   = sF + BAS_OFF + buf * SB_WORDS;

#pragma unroll
        for (int ks = 0; ks < 2; ++ks) {
            const int kb = ks * 8;
            const int r1 = (kb + tig) * PITCH_A;
            const int r2 = (kb + tig + 4) * PITCH_A;
            uint32_t a[2][4];
#pragma unroll
            for (int mt = 0; mt < 2; ++mt) {
                const int m0 = mbase + mt * 16 + g;
                a[mt][0] = f2tf32(fMix[r1 + m0]     * fMsk[r1 + m0]);
                a[mt][1] = f2tf32(fMix[r1 + m0 + 8] * fMsk[r1 + m0 + 8]);
                a[mt][2] = f2tf32(fMix[r2 + m0]     * fMsk[r2 + m0]);
                a[mt][3] = f2tf32(fMix[r2 + m0 + 8] * fMsk[r2 + m0 + 8]);
            }
            uint32_t bf[5][2];
#pragma unroll
            for (int nt = 0; nt < 5; ++nt) {
                bf[nt][0] = f2tf32(fB[(nt * 8 + g) * PITCH_B + kb + tig]);
                bf[nt][1] = f2tf32(fB[(nt * 8 + g) * PITCH_B + kb + tig + 4]);
            }
#pragma unroll
            for (int mt = 0; mt < 2; ++mt)
#pragma unroll
                for (int nt = 0; nt < 5; ++nt)
                    mma_tf32(acc[mt][nt], a[mt], bf[nt]);
        }
    }

    // ---- write frags to D tile in SMEM (overlay; loop buffers dead) ----
    __syncthreads();
#pragma unroll
    for (int mt = 0; mt < 2; ++mt) {
#pragma unroll
        for (int nt = 0; nt < 5; ++nt) {
            int row = wch * MTILE + mbase + mt * 16 + g;
            int col = nt * 8 + 2 * tig;
            *reinterpret_cast<float2*>(&sD[row * PITCH_D + col]) =
                make_float2(acc[mt][nt][0], acc[mt][nt][1]);
            *reinterpret_cast<float2*>(&sD[(row + 8) * PITCH_D + col]) =
                make_float2(acc[mt][nt][2], acc[mt][nt][3]);
        }
    }

    // ---- boundary frame: warp w computes 5 of the 40 (ch,j) values in fp32 ----
    if (ltile > 0) {
#pragma unroll
        for (int pi = 0; pi < 5; ++pi) {
            const int p = wid * 5 + pi;            // 0..39; ch = p/20 == wch
            const int j = p - wch * STEP;          // 0..19
            float partial = 0.f;
#pragma unroll
            for (int k = 0; k < 8; ++k)
                partial += scol[k] * __ldg(&basis[(size_t)(STEP + j) * E_DIM + lane + 32 * k]);
#pragma unroll
            for (int off = 16; off; off >>= 1)
                partial += __shfl_down_sync(0xffffffffu, partial, off);
            if (lane == 0) sBnd[wch * STEP + j] = partial;
        }
    }
    __syncthreads();

    // ---- overlap-add epilogue: all plain stores, no atomics ----
    const int r  = tid & 127;
    const int rr = mch * MTILE + r;        // sD row
    const int l  = ltile * MTILE + r;

    float lo[STEP], up[STEP];
#pragma unroll
    for (int q = 0; q < 5; ++q) {
        float4 v = *reinterpret_cast<float4*>(&sD[rr * PITCH_D + q * 4]);
        lo[4 * q] = v.x; lo[4 * q + 1] = v.y; lo[4 * q + 2] = v.z; lo[4 * q + 3] = v.w;
    }
    if (r > 0) {
#pragma unroll
        for (int q = 0; q < 5; ++q) {
            float4 v = *reinterpret_cast<float4*>(&sD[(rr - 1) * PITCH_D + STEP + q * 4]);
            up[4 * q] = v.x; up[4 * q + 1] = v.y; up[4 * q + 2] = v.z; up[4 * q + 3] = v.w;
        }
    } else if (l > 0) {
#pragma unroll
        for (int j = 0; j < STEP; ++j) up[j] = sBnd[mch * STEP + j];   // recomputed frame l-1
    } else {
#pragma unroll
        for (int j = 0; j < STEP; ++j) up[j] = 0.f;                    // l==0: no predecessor
    }

    const size_t base = ((size_t)b * C_DIM + mch) * T_DIM + (size_t)l * STEP;
#pragma unroll
    for (int j = 0; j < STEP; ++j) out[base + j] = lo[j] + up[j];

    if (r == MTILE - 1 && l == L_DIM - 1) {   // global tail: sole contributor
#pragma unroll
        for (int q = 0; q < 5; ++q) {
            float4 v = *reinterpret_cast<float4*>(&sD[rr * PITCH_D + STEP + q * 4]);
            out[base + STEP + 4 * q]     = v.x;
            out[base + STEP + 4 * q + 1] = v.y;
            out[base + STEP + 4 * q + 2] = v.z;
            out[base + STEP + 4 * q + 3] = v.w;
        }
    }
}

extern "C" void kernel_launch(void* const* d_in, const int* in_sizes, int n_in,
                              void* d_out, int out_size) {
    // Identify inputs by element count for robustness.
    const float *mix = nullptr, *mask = nullptr, *basis = nullptr;
    for (int i = 0; i < n_in; ++i) {
        long long s = in_sizes[i];
        if (s == (long long)B_DIM * E_DIM * L_DIM)              mix   = (const float*)d_in[i];
        else if (s == (long long)B_DIM * C_DIM * E_DIM * L_DIM) mask  = (const float*)d_in[i];
        else if (s == (long long)W_DIM * E_DIM)                 basis = (const float*)d_in[i];
    }
    float* out = (float*)d_out;

    cudaFuncSetAttribute(decoder_kernel,
                         cudaFuncAttributeMaxDynamicSharedMemorySize, SMEM_BYTES);
    decoder_kernel<<<B_DIM * LTILES, NT, SMEM_BYTES>>>(mix, mask, basis, out);
}

// round 15
// speedup vs baseline: 1.1855x; 1.1476x over previous
#include <cuda_runtime.h>
#include <stdint.h>

#define B_DIM 4
#define C_DIM 2
#define E_DIM 256
#define L_DIM 16000
#define W_DIM 40
#define STEP  20
#define T_DIM ((L_DIM - 1) * STEP + W_DIM)   // 320020
#define NT    256
#define MTILE 128                  // l's per CTA
#define LTILES (L_DIM / MTILE)     // 125
#define NCTAS (B_DIM * LTILES)     // 500

#define KC      16
#define NSTAGE  (E_DIM / KC)       // 16
#define NBUF    3
#define PITCH_A 136                // words; mod 32 == 8 -> conflict-free frag reads
#define PITCH_B 20                 // words; (nt*8+g)*20 + tig distinct mod 32
#define PITCH_D 40

#define SA_WORDS (KC * PITCH_A)        // 2176 per buffer
#define SB_WORDS (W_DIM * PITCH_B)     // 800 per buffer
#define MIX_OFF  0                                  // 3 bufs
#define MSK_OFF  (NBUF * SA_WORDS)                  // 6528; 3 bufs x 2 channels
#define BAS_OFF  (MSK_OFF + 2 * NBUF * SA_WORDS)    // 19584
#define LOOP_WORDS (BAS_OFF + NBUF * SB_WORDS)      // 21984
#define SMEM_BYTES (LOOP_WORDS * 4)                 // 87936

// ---- inter-CTA boundary mailbox (producer bid -> consumer bid+4) ----
__device__ float g_bnd[NCTAS * C_DIM * STEP];   // producer's row-127 upper halves
__device__ int   g_flag[NCTAS];                 // zero-init at module load; consumer resets

__device__ __forceinline__ uint32_t f2tf32(float f) {
    uint32_t u;
    asm("cvt.rna.tf32.f32 %0, %1;" : "=r"(u) : "f"(f));
    return u;
}
__device__ __forceinline__ void mma_tf32(float* d, const uint32_t* a, const uint32_t* b) {
    asm volatile(
        "mma.sync.aligned.m16n8k8.row.col.f32.tf32.tf32.f32 "
        "{%0,%1,%2,%3}, {%4,%5,%6,%7}, {%8,%9}, {%0,%1,%2,%3};"
        : "+f"(d[0]), "+f"(d[1]), "+f"(d[2]), "+f"(d[3])
        : "r"(a[0]), "r"(a[1]), "r"(a[2]), "r"(a[3]), "r"(b[0]), "r"(b[1]));
}
__device__ __forceinline__ void cp16(uint32_t dst_smem, const void* src) {
    asm volatile("cp.async.cg.shared.global [%0], [%1], 16;" :: "r"(dst_smem), "l"(src));
}
__device__ __forceinline__ void cp_commit() {
    asm volatile("cp.async.commit_group;" ::: "memory");
}
__device__ __forceinline__ void cp_wait1() {
    asm volatile("cp.async.wait_group 1;" ::: "memory");
}

__global__ void __launch_bounds__(NT, 2)
decoder_kernel(const float* __restrict__ mix,
               const float* __restrict__ mask,
               const float* __restrict__ basis,
               float* __restrict__ out) {
    extern __shared__ __align__(16) uint32_t smem[];
    const uint32_t smem_base = (uint32_t)__cvta_generic_to_shared(smem);
    float* sF = reinterpret_cast<float*>(smem);
    float* sD = sF;                                  // epilogue overlay (2*128*40 words)

    const int tid  = threadIdx.x;
    const int wid  = tid >> 5;
    const int lane = tid & 31;
    const int g    = lane >> 2;
    const int tig  = lane & 3;

    const int bid   = blockIdx.x;
    const int b     = bid & 3;
    const int ltile = bid >> 2;

    const float* pmix = mix + (size_t)b * E_DIM * L_DIM + (size_t)ltile * MTILE;
    const float* pmk0 = mask + ((size_t)b * C_DIM + 0) * E_DIM * L_DIM + (size_t)ltile * MTILE;
    const float* pmk1 = pmk0 + (size_t)E_DIM * L_DIM;

    // staging coords: mix -> 2 quads/thread, mask -> my channel, 4 quads/thread
    const int mch  = tid >> 7;             // which mask channel this thread stages
    const int mt7  = tid & 127;
    const float* pmk = (mch == 0) ? pmk0 : pmk1;

    float acc[2][5][4];
#pragma unroll
    for (int mt = 0; mt < 2; ++mt)
#pragma unroll
        for (int nt = 0; nt < 5; ++nt)
#pragma unroll
            for (int r = 0; r < 4; ++r) acc[mt][nt][r] = 0.f;

    // ---- stage issuer (cp.async) ----
    auto issue_stage = [&](int s) {
        if (s < NSTAGE) {
            const int buf = s % NBUF;
            const size_t eoff = (size_t)s * KC * L_DIM;
            const uint32_t dmix = smem_base + (MIX_OFF + buf * SA_WORDS) * 4;
            const uint32_t dmsk = smem_base + (MSK_OFF + (buf * 2 + mch) * SA_WORDS) * 4;
            // mix: 512 quads over 256 threads (2 each)
#pragma unroll
            for (int i = 0; i < 2; ++i) {
                const int q = tid + (i << 8);
                const int e = q >> 5, l4 = (q & 31) * 4;
                cp16(dmix + (uint32_t)(e * PITCH_A + l4) * 4,
                     pmix + eoff + (size_t)e * L_DIM + l4);
            }
            // mask (my channel): 512 quads over 128 threads (4 each)
#pragma unroll
            for (int i = 0; i < 4; ++i) {
                const int q = mt7 + (i << 7);
                const int e = q >> 5, l4 = (q & 31) * 4;
                cp16(dmsk + (uint32_t)(e * PITCH_A + l4) * 4,
                     pmk + eoff + (size_t)e * L_DIM + l4);
            }
            // basis chunk: 160 quads
            if (tid < 160) {
                const int w = tid >> 2, be = (tid & 3) * 4;
                const uint32_t dbas = smem_base + (BAS_OFF + buf * SB_WORDS) * 4;
                cp16(dbas + (uint32_t)(w * PITCH_B + be) * 4,
                     basis + (size_t)w * E_DIM + s * KC + be);
            }
        }
        cp_commit();   // empty groups past the end keep wait counts uniform
    };

    // prologue: stages 0 and 1 in flight
    issue_stage(0);
    issue_stage(1);

    const int ch    = wid >> 2;            // compute channel of this warp
    const int mbase = (wid & 3) * 32;

#pragma unroll 1
    for (int st = 0; st < NSTAGE; ++st) {
        cp_wait1();                 // stage st landed (st+1 still in flight)
        __syncthreads();            // stage st visible; all warps past mma(st-1)
        issue_stage(st + 2);        // buf (st+2)%3 == (st-1)%3: freed by the sync above

        const int buf = st % NBUF;
        const float* fMix = sF + MIX_OFF + buf * SA_WORDS;
        const float* fMsk = sF + MSK_OFF + (buf * 2 + ch) * SA_WORDS;
        const float* fB   = sF + BAS_OFF + buf * SB_WORDS;

#pragma unroll
        for (int ks = 0; ks < 2; ++ks) {
            const int kb = ks * 8;
            const int r1 = (kb + tig) * PITCH_A;
            const int r2 = (kb + tig + 4) * PITCH_A;
            uint32_t a[2][4];
#pragma unroll
            for (int mt = 0; mt < 2; ++mt) {
                const int m0 = mbase + mt * 16 + g;
                a[mt][0] = f2tf32(fMix[r1 + m0]     * fMsk[r1 + m0]);
                a[mt][1] = f2tf32(fMix[r1 + m0 + 8] * fMsk[r1 + m0 + 8]);
                a[mt][2] = f2tf32(fMix[r2 + m0]     * fMsk[r2 + m0]);
                a[mt][3] = f2tf32(fMix[r2 + m0 + 8] * fMsk[r2 + m0 + 8]);
            }
            uint32_t bf[5][2];
#pragma unroll
            for (int nt = 0; nt < 5; ++nt) {
                bf[nt][0] = f2tf32(fB[(nt * 8 + g) * PITCH_B + kb + tig]);
                bf[nt][1] = f2tf32(fB[(nt * 8 + g) * PITCH_B + kb + tig + 4]);
            }
#pragma unroll
            for (int mt = 0; mt < 2; ++mt)
#pragma unroll
                for (int nt = 0; nt < 5; ++nt)
                    mma_tf32(acc[mt][nt], a[mt], bf[nt]);
        }
    }

    // ---- write frags to D tile in SMEM (overlay; loop buffers dead) ----
    __syncthreads();
#pragma unroll
    for (int mt = 0; mt < 2; ++mt) {
#pragma unroll
        for (int nt = 0; nt < 5; ++nt) {
            int row = ch * MTILE + mbase + mt * 16 + g;
            int col = nt * 8 + 2 * tig;
            *reinterpret_cast<float2*>(&sD[row * PITCH_D + col]) =
                make_float2(acc[mt][nt][0], acc[mt][nt][1]);
            *reinterpret_cast<float2*>(&sD[(row + 8) * PITCH_D + col]) =
                make_float2(acc[mt][nt][2], acc[mt][nt][3]);
        }
    }
    __syncthreads();

    // ---- PRODUCE: publish row-127 upper halves (both channels) to the mailbox ----
    if (ltile < LTILES - 1) {
        if (tid < C_DIM * STEP) {
            const int pch = tid / STEP, j = tid % STEP;
            g_bnd[(bid * C_DIM + pch) * STEP + j] =
                sD[(pch * MTILE + MTILE - 1) * PITCH_D + STEP + j];
        }
        __syncthreads();
        if (tid == 0) {
            __threadfence();
            atomicExch(&g_flag[bid], 1);    // release
        }
    }

    // ---- CONSUME + overlap-add epilogue: all plain stores, no atomics on out ----
    const int r  = tid & 127;
    const int rr = mch * MTILE + r;        // sD row
    const int l  = ltile * MTILE + r;

    float lo[STEP], up[STEP];
#pragma unroll
    for (int q = 0; q < 5; ++q) {
        float4 v = *reinterpret_cast<float4*>(&sD[rr * PITCH_D + q * 4]);
        lo[4 * q] = v.x; lo[4 * q + 1] = v.y; lo[4 * q + 2] = v.z; lo[4 * q + 3] = v.w;
    }
    if (r > 0) {
#pragma unroll
        for (int q = 0; q < 5; ++q) {
            float4 v = *reinterpret_cast<float4*>(&sD[(rr - 1) * PITCH_D + STEP + q * 4]);
            up[4 * q] = v.x; up[4 * q + 1] = v.y; up[4 * q + 2] = v.z; up[4 * q + 3] = v.w;
        }
    } else if (ltile > 0) {
        // spin for producer bid-4 (scheduled no later than us; publishes before consuming)
        const int p = bid - 4;
        while (atomicAdd(&g_flag[p], 0) == 0) {}
        __threadfence();                    // acquire
#pragma unroll
        for (int j = 0; j < STEP; ++j)
            up[j] = g_bnd[(p * C_DIM + mch) * STEP + j];
    } else {
#pragma unroll
        for (int j = 0; j < STEP; ++j) up[j] = 0.f;   // l==0: no predecessor
    }

    const size_t base = ((size_t)b * C_DIM + mch) * T_DIM + (size_t)l * STEP;
#pragma unroll
    for (int j = 0; j < STEP; ++j) out[base + j] = lo[j] + up[j];

    if (r == MTILE - 1 && l == L_DIM - 1) {   // global tail: sole contributor
#pragma unroll
        for (int q = 0; q < 5; ++q) {
            float4 v = *reinterpret_cast<float4*>(&sD[rr * PITCH_D + STEP + q * 4]);
            out[base + STEP + 4 * q]     = v.x;
            out[base + STEP + 4 * q + 1] = v.y;
            out[base + STEP + 4 * q + 2] = v.z;
            out[base + STEP + 4 * q + 3] = v.w;
        }
    }

    // ---- reset consumed flag so the next graph replay starts clean ----
    __syncthreads();                        // both consumers (tid 0,128) done reading
    if (tid == 0 && ltile > 0) g_flag[bid - 4] = 0;
}

extern "C" void kernel_launch(void* const* d_in, const int* in_sizes, int n_in,
                              void* d_out, int out_size) {
    // Identify inputs by element count for robustness.
    const float *mix = nullptr, *mask = nullptr, *basis = nullptr;
    for (int i = 0; i < n_in; ++i) {
        long long s = in_sizes[i];
        if (s == (long long)B_DIM * E_DIM * L_DIM)              mix   = (const float*)d_in[i];
        else if (s == (long long)B_DIM * C_DIM * E_DIM * L_DIM) mask  = (const float*)d_in[i];
        else if (s == (long long)W_DIM * E_DIM)                 basis = (const float*)d_in[i];
    }
    float* out = (float*)d_out;

    cudaFuncSetAttribute(decoder_kernel,
                         cudaFuncAttributeMaxDynamicSharedMemorySize, SMEM_BYTES);
    decoder_kernel<<<NCTAS, NT, SMEM_BYTES>>>(mix, mask, basis, out);
}